// round 2
// baseline (speedup 1.0000x reference)
#include <cuda_runtime.h>
#include <cuda_bf16.h>
#include <math.h>

#define FEAT   19
#define NANCH  9
#define P_TOT  (FEAT*FEAT*NANCH)   // 3249
#define NCLS   21
#define NOBJ   12
#define B_MAX  256
#define NT     512

__device__ float g_ll[B_MAX];
__device__ float g_lc[B_MAX];
__device__ float g_np[B_MAX];

// block-wide sum over NT=512 threads
__device__ __forceinline__ float blkSum(float v, float* sW) {
    int tid = threadIdx.x;
    #pragma unroll
    for (int o = 16; o > 0; o >>= 1) v += __shfl_down_sync(0xFFFFFFFFu, v, o);
    if ((tid & 31) == 0) sW[tid >> 5] = v;
    __syncthreads();
    if (tid < 32) {
        float w = (tid < NT / 32) ? sW[tid] : 0.0f;
        #pragma unroll
        for (int o = 8; o > 0; o >>= 1) w += __shfl_down_sync(0xFFFFFFFFu, w, o);
        if (tid == 0) sW[0] = w;
    }
    __syncthreads();
    float r = sW[0];
    __syncthreads();
    return r;
}

__global__ __launch_bounds__(NT)
void multibox_loss_kernel(const float* __restrict__ loc,
                          const float* __restrict__ conf,
                          const float* __restrict__ priors,
                          const float* __restrict__ targets,
                          float* __restrict__ out, int B)
{
    __shared__ float sVal[P_TOT];              // best_truth_ov -> loss_c_mine
    __shared__ unsigned char sConf[P_TOT];     // best_truth_idx -> conf_t
    __shared__ unsigned char sSel[P_TOT];      // pos|neg mask
    __shared__ unsigned long long sBP[NOBJ];   // packed (ov, ~prior) per truth
    __shared__ float sT[NOBJ][4];
    __shared__ float sTA[NOBJ];
    __shared__ int   sLab[NOBJ];
    __shared__ float sW[32];

    const int b   = blockIdx.x;
    const int tid = threadIdx.x;

    // ---- load truths (exact IEEE, matching reference order) ----
    const float* tg = targets + (size_t)b * NOBJ * 5;
    if (tid < NOBJ) {
        float x1 = tg[tid*5+0], y1 = tg[tid*5+1];
        float x2 = tg[tid*5+2], y2 = tg[tid*5+3];
        sT[tid][0]=x1; sT[tid][1]=y1; sT[tid][2]=x2; sT[tid][3]=y2;
        sTA[tid] = __fmul_rn(__fsub_rn(x2, x1), __fsub_rn(y2, y1));
        sLab[tid] = (int)tg[tid*5+4];
        sBP[tid] = 0ULL;
    }
    __syncthreads();

    // ---- phase 1: matching (bit-exact jaccard: no FMA contraction,
    //      area_b from point-form coords exactly as reference) ----
    unsigned long long bp[NOBJ];
    #pragma unroll
    for (int t = 0; t < NOBJ; t++) bp[t] = 0ULL;

    for (int p = tid; p < P_TOT; p += NT) {
        float4 pr = __ldg((const float4*)priors + p);
        float hw = __fmul_rn(0.5f, pr.z);
        float hh = __fmul_rn(0.5f, pr.w);
        float px1 = __fsub_rn(pr.x, hw), py1 = __fsub_rn(pr.y, hh);
        float px2 = __fadd_rn(pr.x, hw), py2 = __fadd_rn(pr.y, hh);
        float ap  = __fmul_rn(__fsub_rn(px2, px1), __fsub_rn(py2, py1));
        float best = -1.0f; int bt = 0;
        #pragma unroll
        for (int t = 0; t < NOBJ; t++) {
            float iw = __fsub_rn(fminf(sT[t][2], px2), fmaxf(sT[t][0], px1));
            float ih = __fsub_rn(fminf(sT[t][3], py2), fmaxf(sT[t][1], py1));
            iw = fmaxf(iw, 0.0f); ih = fmaxf(ih, 0.0f);
            float inter = __fmul_rn(iw, ih);
            float uni   = __fsub_rn(__fadd_rn(sTA[t], ap), inter);
            float ov    = __fdiv_rn(inter, uni);
            if (ov > best) { best = ov; bt = t; }   // first-max over t (argmax axis=0)
            unsigned long long pk =
                (((unsigned long long)__float_as_uint(ov)) << 32)
                | (unsigned)(0xFFFFFFFFu - (unsigned)p);   // smaller p wins ties
            if (pk > bp[t]) bp[t] = pk;
        }
        sVal[p]  = best;
        sConf[p] = (unsigned char)bt;
    }
    #pragma unroll
    for (int t = 0; t < NOBJ; t++) atomicMax(&sBP[t], bp[t]);
    __syncthreads();

    // forced match: serial last-wins (sequential scatter semantics)
    if (tid == 0) {
        for (int t = 0; t < NOBJ; t++) {
            unsigned p = 0xFFFFFFFFu - (unsigned)(sBP[t] & 0xFFFFFFFFull);
            sVal[p]  = 2.0f;
            sConf[p] = (unsigned char)t;
        }
    }
    __syncthreads();

    // ---- phase 2: conf_t, CE, positive loc loss ----
    float lossl = 0.0f, posce = 0.0f, npos = 0.0f;
    for (int p = tid; p < P_TOT; p += NT) {
        int t = sConf[p];
        float ov = sVal[p];
        int cf = 0;
        if (!(ov < 0.5f)) cf = sLab[t] + 1;

        const float* cp = conf + ((size_t)b * P_TOT + p) * NCLS;
        float x[NCLS];
        #pragma unroll
        for (int i = 0; i < NCLS; i++) x[i] = __ldg(cp + i);
        float m = x[0];
        #pragma unroll
        for (int i = 1; i < NCLS; i++) m = fmaxf(m, x[i]);
        float s = 0.0f;
        #pragma unroll
        for (int i = 0; i < NCLS; i++) s += __expf(x[i] - m);
        float g = x[0];
        #pragma unroll
        for (int i = 1; i < NCLS; i++) if (i == cf) g = x[i];
        float ce = m + __logf(s) - g;

        if (cf > 0) {
            npos  += 1.0f;
            posce += ce;
            float4 ld = __ldg((const float4*)loc + (size_t)b * P_TOT + p);
            float4 pr = __ldg((const float4*)priors + p);
            float tx1 = sT[t][0], ty1 = sT[t][1], tx2 = sT[t][2], ty2 = sT[t][3];
            float e0 = ((tx1 + tx2) * 0.5f - pr.x) / (0.1f * pr.z);
            float e1 = ((ty1 + ty2) * 0.5f - pr.y) / (0.1f * pr.w);
            float e2 = logf((tx2 - tx1) / pr.z) * 5.0f;
            float e3 = logf((ty2 - ty1) / pr.w) * 5.0f;
            float d, ad;
            d = ld.x - e0; ad = fabsf(d); lossl += (ad < 1.0f) ? 0.5f*d*d : ad - 0.5f;
            d = ld.y - e1; ad = fabsf(d); lossl += (ad < 1.0f) ? 0.5f*d*d : ad - 0.5f;
            d = ld.z - e2; ad = fabsf(d); lossl += (ad < 1.0f) ? 0.5f*d*d : ad - 0.5f;
            d = ld.w - e3; ad = fabsf(d); lossl += (ad < 1.0f) ? 0.5f*d*d : ad - 0.5f;
            sVal[p] = 0.0f;           // loss_c_mine = 0 at positives
        } else {
            sVal[p] = ce;
        }
        sConf[p] = (unsigned char)cf;
    }
    __syncthreads();

    float npos_t  = blkSum(npos,  sW);
    float posce_t = blkSum(posce, sW);
    float lossl_t = blkSum(lossl, sW);
    int np = (int)npos_t;
    int k  = min(3 * np, P_TOT - 1);          // num_neg

    // ---- phase 3: radix select k-th largest of sVal (all values >= 0) ----
    unsigned prefix = 0;
    int kk = k;
    for (int bit = 31; bit >= 0; --bit) {
        unsigned cand = prefix | (1u << bit);
        unsigned mask = ~((1u << bit) - 1u);
        float lc = 0.0f;
        for (int p = tid; p < P_TOT; p += NT) {
            unsigned u = __float_as_uint(sVal[p]);
            lc += ((u & mask) == cand) ? 1.0f : 0.0f;
        }
        int c = (int)blkSum(lc, sW);
        if (c >= kk) prefix = cand; else kk -= c;
    }

    float eqc = 0.0f;
    for (int p = tid; p < P_TOT; p += NT)
        eqc += (__float_as_uint(sVal[p]) == prefix) ? 1.0f : 0.0f;
    int ceq = (int)blkSum(eqc, sW);

    // ---- phase 4: sel mask + hard-negative CE sum ----
    float negsum = 0.0f;
    for (int p = tid; p < P_TOT; p += NT) {
        int pos = sConf[p] > 0;
        unsigned u = __float_as_uint(sVal[p]);
        int sel = pos;
        if (u > prefix) sel = 1;
        else if (u == prefix) {
            if (kk >= ceq) sel = 1;
            else {
                int r = 0;                     // stable index-rank among equals
                for (int q = 0; q < p; q++)
                    r += (__float_as_uint(sVal[q]) == prefix) ? 1 : 0;
                if (r < kk) sel = 1;
            }
        }
        if (sel && !pos) negsum += sVal[p];
        sSel[p] = (unsigned char)sel;
    }
    float lossc_t = posce_t + blkSum(negsum, sW);
    __syncthreads();

    // ---- phase 5: per-cell featuremaps ----
    for (int c = tid; c < FEAT * FEAT; c += NT) {
        int base = c * NANCH;
        int mc = 0, ms = 0;
        #pragma unroll
        for (int a = 0; a < NANCH; a++) {
            mc = max(mc, (int)sConf[base + a]);
            ms = max(ms, (int)sSel[base + a]);
        }
        out[2 + (size_t)b * (FEAT*FEAT) + c]                           = (float)mc;
        out[2 + (size_t)B * (FEAT*FEAT) + (size_t)b * (FEAT*FEAT) + c] = (float)ms;
    }

    if (tid == 0) {
        g_ll[b] = lossl_t;
        g_lc[b] = lossc_t;
        g_np[b] = npos_t;
    }
}

__global__ void finalize_kernel(float* __restrict__ out, int B)
{
    __shared__ float sW[32];
    int tid = threadIdx.x;
    float ll = (tid < B) ? g_ll[tid] : 0.0f;
    float lc = (tid < B) ? g_lc[tid] : 0.0f;
    float np = (tid < B) ? g_np[tid] : 0.0f;
    #pragma unroll
    for (int o = 16; o > 0; o >>= 1) {
        ll += __shfl_down_sync(0xFFFFFFFFu, ll, o);
        lc += __shfl_down_sync(0xFFFFFFFFu, lc, o);
        np += __shfl_down_sync(0xFFFFFFFFu, np, o);
    }
    if ((tid & 31) == 0) { sW[(tid>>5)] = ll; sW[8+(tid>>5)] = lc; sW[16+(tid>>5)] = np; }
    __syncthreads();
    if (tid == 0) {
        float L = 0, C = 0, N = 0;
        for (int w = 0; w < 8; w++) { L += sW[w]; C += sW[8+w]; N += sW[16+w]; }
        out[0] = L / N;
        out[1] = C / N;
    }
}

extern "C" void kernel_launch(void* const* d_in, const int* in_sizes, int n_in,
                              void* d_out, int out_size)
{
    const float* loc     = (const float*)d_in[0];
    const float* conf    = (const float*)d_in[1];
    const float* priors  = (const float*)d_in[2];
    const float* targets = (const float*)d_in[3];
    float* out = (float*)d_out;

    int B = in_sizes[3] / (NOBJ * 5);   // 256

    multibox_loss_kernel<<<B, NT>>>(loc, conf, priors, targets, out, B);
    finalize_kernel<<<1, 256>>>(out, B);
}

// round 5
// speedup vs baseline: 1.0903x; 1.0903x over previous
#include <cuda_runtime.h>
#include <cuda_bf16.h>
#include <math.h>

#define FEAT   19
#define NANCH  9
#define P_TOT  (FEAT*FEAT*NANCH)   // 3249
#define NCLS   21
#define NOBJ   12
#define B_MAX  256
#define NT     512
#define TA     256                  // priors per block in lse kernel
#define NBLK_A ((P_TOT + TA - 1) / TA)   // 13

__device__ float g_ll[B_MAX];
__device__ float g_lc[B_MAX];
__device__ float g_np[B_MAX];
__device__ float g_lse[B_MAX * P_TOT];
__device__ float g_x0 [B_MAX * P_TOT];

// ---------------- kernel A: coalesced logsumexp precompute ----------------
__global__ __launch_bounds__(TA)
void lse_kernel(const float* __restrict__ conf)
{
    __shared__ float s[TA * NCLS];   // 21504 B
    const int b  = blockIdx.y;
    const int p0 = blockIdx.x * TA;
    const int np = min(TA, P_TOT - p0);
    const int tot = np * NCLS;
    const float* base = conf + ((size_t)b * P_TOT + p0) * NCLS;
    const int tid = threadIdx.x;

    for (int i = tid; i < tot; i += TA) s[i] = base[i];
    __syncthreads();

    if (tid < np) {
        const float* x = s + tid * NCLS;
        float m = x[0];
        #pragma unroll
        for (int i = 1; i < NCLS; i++) m = fmaxf(m, x[i]);
        float sum = 0.0f;
        #pragma unroll
        for (int i = 0; i < NCLS; i++) sum += __expf(x[i] - m);
        size_t o = (size_t)b * P_TOT + p0 + tid;
        g_lse[o] = m + __logf(sum);
        g_x0 [o] = x[0];
    }
}

// block-wide sum over NT=512 threads
__device__ __forceinline__ float blkSum(float v, float* sW) {
    int tid = threadIdx.x;
    #pragma unroll
    for (int o = 16; o > 0; o >>= 1) v += __shfl_down_sync(0xFFFFFFFFu, v, o);
    if ((tid & 31) == 0) sW[tid >> 5] = v;
    __syncthreads();
    if (tid < 32) {
        float w = (tid < NT / 32) ? sW[tid] : 0.0f;
        #pragma unroll
        for (int o = 8; o > 0; o >>= 1) w += __shfl_down_sync(0xFFFFFFFFu, w, o);
        if (tid == 0) sW[0] = w;
    }
    __syncthreads();
    float r = sW[0];
    __syncthreads();
    return r;
}

// ---------------- kernel B: per-batch matching / select / featuremaps ------
__global__ __launch_bounds__(NT)
void multibox_loss_kernel(const float* __restrict__ loc,
                          const float* __restrict__ conf,
                          const float* __restrict__ priors,
                          const float* __restrict__ targets,
                          float* __restrict__ out, int B)
{
    __shared__ float sVal[P_TOT];
    __shared__ unsigned char sConf[P_TOT];
    __shared__ unsigned char sSel[P_TOT];
    __shared__ unsigned long long sBP[NOBJ];
    __shared__ float sT[NOBJ][4];
    __shared__ float sTA[NOBJ];
    __shared__ int   sLab[NOBJ];
    __shared__ float sW[32];
    __shared__ int   hist[256];
    __shared__ unsigned sDig[2];

    const int b   = blockIdx.x;
    const int tid = threadIdx.x;

    const float* tg = targets + (size_t)b * NOBJ * 5;
    if (tid < NOBJ) {
        float x1 = tg[tid*5+0], y1 = tg[tid*5+1];
        float x2 = tg[tid*5+2], y2 = tg[tid*5+3];
        sT[tid][0]=x1; sT[tid][1]=y1; sT[tid][2]=x2; sT[tid][3]=y2;
        sTA[tid] = __fmul_rn(__fsub_rn(x2, x1), __fsub_rn(y2, y1));
        sLab[tid] = (int)tg[tid*5+4];
        sBP[tid] = 0ULL;
    }
    __syncthreads();

    // ---- phase 1: matching (bit-exact jaccard) ----
    unsigned long long bp[NOBJ];
    #pragma unroll
    for (int t = 0; t < NOBJ; t++) bp[t] = 0ULL;

    for (int p = tid; p < P_TOT; p += NT) {
        float4 pr = __ldg((const float4*)priors + p);
        float hw = __fmul_rn(0.5f, pr.z);
        float hh = __fmul_rn(0.5f, pr.w);
        float px1 = __fsub_rn(pr.x, hw), py1 = __fsub_rn(pr.y, hh);
        float px2 = __fadd_rn(pr.x, hw), py2 = __fadd_rn(pr.y, hh);
        float ap  = __fmul_rn(__fsub_rn(px2, px1), __fsub_rn(py2, py1));
        float best = -1.0f; int bt = 0;
        #pragma unroll
        for (int t = 0; t < NOBJ; t++) {
            float iw = __fsub_rn(fminf(sT[t][2], px2), fmaxf(sT[t][0], px1));
            float ih = __fsub_rn(fminf(sT[t][3], py2), fmaxf(sT[t][1], py1));
            iw = fmaxf(iw, 0.0f); ih = fmaxf(ih, 0.0f);
            float inter = __fmul_rn(iw, ih);
            float uni   = __fsub_rn(__fadd_rn(sTA[t], ap), inter);
            float ov    = __fdiv_rn(inter, uni);
            if (ov > best) { best = ov; bt = t; }
            unsigned long long pk =
                (((unsigned long long)__float_as_uint(ov)) << 32)
                | (unsigned)(0xFFFFFFFFu - (unsigned)p);
            if (pk > bp[t]) bp[t] = pk;
        }
        sVal[p]  = best;
        sConf[p] = (unsigned char)bt;
    }
    #pragma unroll
    for (int t = 0; t < NOBJ; t++) atomicMax(&sBP[t], bp[t]);
    __syncthreads();

    if (tid == 0) {
        for (int t = 0; t < NOBJ; t++) {
            unsigned p = 0xFFFFFFFFu - (unsigned)(sBP[t] & 0xFFFFFFFFull);
            sVal[p]  = 2.0f;
            sConf[p] = (unsigned char)t;
        }
    }
    __syncthreads();

    // ---- phase 2: conf_t, CE from scratch, positive loc loss ----
    const float* plse = g_lse + (size_t)b * P_TOT;
    const float* px0  = g_x0  + (size_t)b * P_TOT;
    float lossl = 0.0f, posce = 0.0f, npos = 0.0f;
    for (int p = tid; p < P_TOT; p += NT) {
        int t = sConf[p];
        float ov = sVal[p];
        int cf = 0;
        if (!(ov < 0.5f)) cf = sLab[t] + 1;

        float lse = plse[p];
        if (cf > 0) {
            float g = __ldg(conf + ((size_t)b * P_TOT + p) * NCLS + cf);
            float ce = lse - g;
            npos  += 1.0f;
            posce += ce;
            float4 ld = __ldg((const float4*)loc + (size_t)b * P_TOT + p);
            float4 pr = __ldg((const float4*)priors + p);
            float tx1 = sT[t][0], ty1 = sT[t][1], tx2 = sT[t][2], ty2 = sT[t][3];
            float e0 = ((tx1 + tx2) * 0.5f - pr.x) / (0.1f * pr.z);
            float e1 = ((ty1 + ty2) * 0.5f - pr.y) / (0.1f * pr.w);
            float e2 = logf((tx2 - tx1) / pr.z) * 5.0f;
            float e3 = logf((ty2 - ty1) / pr.w) * 5.0f;
            float d, ad;
            d = ld.x - e0; ad = fabsf(d); lossl += (ad < 1.0f) ? 0.5f*d*d : ad - 0.5f;
            d = ld.y - e1; ad = fabsf(d); lossl += (ad < 1.0f) ? 0.5f*d*d : ad - 0.5f;
            d = ld.z - e2; ad = fabsf(d); lossl += (ad < 1.0f) ? 0.5f*d*d : ad - 0.5f;
            d = ld.w - e3; ad = fabsf(d); lossl += (ad < 1.0f) ? 0.5f*d*d : ad - 0.5f;
            sVal[p] = 0.0f;
        } else {
            sVal[p] = lse - px0[p];
        }
        sConf[p] = (unsigned char)cf;
    }
    __syncthreads();

    float npos_t  = blkSum(npos,  sW);
    float posce_t = blkSum(posce, sW);
    float lossl_t = blkSum(lossl, sW);
    int np = (int)npos_t;
    int k  = min(3 * np, P_TOT - 1);

    // ---- phase 3: 8-bit radix select (k-th largest, values >= 0) ----
    unsigned prefix = 0;
    int kk = k;
    for (int shift = 24; shift >= 0; shift -= 8) {
        if (tid < 256) hist[tid] = 0;
        __syncthreads();
        unsigned hmask = (shift == 24) ? 0u : (0xFFFFFFFFu << (shift + 8));
        for (int p = tid; p < P_TOT; p += NT) {
            unsigned u = __float_as_uint(sVal[p]);
            if ((u & hmask) == (prefix & hmask)) {
                unsigned d = (u >> shift) & 255u;
                unsigned peers = __match_any_sync(__activemask(), d);
                int leader = __ffs(peers) - 1;
                if ((int)(threadIdx.x & 31) == leader)
                    atomicAdd(&hist[d], __popc(peers));
            }
        }
        __syncthreads();
        if (tid < 32) {
            int loc8[8]; int s = 0;
            #pragma unroll
            for (int i = 0; i < 8; i++) { loc8[i] = hist[tid*8 + i]; s += loc8[i]; }
            int v = s;
            #pragma unroll
            for (int off = 1; off < 32; off <<= 1) {
                int t2 = __shfl_down_sync(0xFFFFFFFFu, v, off);
                if (tid + off < 32) v += t2;
            }
            int cgt = v - s;          // count of digits in higher lanes
            #pragma unroll
            for (int i = 7; i >= 0; i--) {
                if (cgt < kk && kk <= cgt + loc8[i]) {
                    sDig[0] = (unsigned)(tid*8 + i);
                    sDig[1] = (unsigned)(kk - cgt);
                }
                cgt += loc8[i];
            }
        }
        __syncthreads();
        prefix |= (sDig[0] << shift);
        kk = (int)sDig[1];
        __syncthreads();
    }

    float eqc = 0.0f;
    for (int p = tid; p < P_TOT; p += NT)
        eqc += (__float_as_uint(sVal[p]) == prefix) ? 1.0f : 0.0f;
    int ceq = (int)blkSum(eqc, sW);

    // ---- phase 4: sel mask + hard-negative CE sum ----
    float negsum = 0.0f;
    for (int p = tid; p < P_TOT; p += NT) {
        int pos = sConf[p] > 0;
        unsigned u = __float_as_uint(sVal[p]);
        int sel = pos;
        if (u > prefix) sel = 1;
        else if (u == prefix) {
            if (kk >= ceq) sel = 1;
            else {
                int r = 0;
                for (int q = 0; q < p; q++)
                    r += (__float_as_uint(sVal[q]) == prefix) ? 1 : 0;
                if (r < kk) sel = 1;
            }
        }
        if (sel && !pos) negsum += sVal[p];
        sSel[p] = (unsigned char)sel;
    }
    float lossc_t = posce_t + blkSum(negsum, sW);
    __syncthreads();

    // ---- phase 5: per-cell featuremaps ----
    for (int c = tid; c < FEAT * FEAT; c += NT) {
        int base = c * NANCH;
        int mc = 0, ms = 0;
        #pragma unroll
        for (int a = 0; a < NANCH; a++) {
            mc = max(mc, (int)sConf[base + a]);
            ms = max(ms, (int)sSel[base + a]);
        }
        out[2 + (size_t)b * (FEAT*FEAT) + c]                           = (float)mc;
        out[2 + (size_t)B * (FEAT*FEAT) + (size_t)b * (FEAT*FEAT) + c] = (float)ms;
    }

    if (tid == 0) {
        g_ll[b] = lossl_t;
        g_lc[b] = lossc_t;
        g_np[b] = npos_t;
    }
}

__global__ void finalize_kernel(float* __restrict__ out, int B)
{
    __shared__ float sW[32];
    int tid = threadIdx.x;
    float ll = (tid < B) ? g_ll[tid] : 0.0f;
    float lc = (tid < B) ? g_lc[tid] : 0.0f;
    float np = (tid < B) ? g_np[tid] : 0.0f;
    #pragma unroll
    for (int o = 16; o > 0; o >>= 1) {
        ll += __shfl_down_sync(0xFFFFFFFFu, ll, o);
        lc += __shfl_down_sync(0xFFFFFFFFu, lc, o);
        np += __shfl_down_sync(0xFFFFFFFFu, np, o);
    }
    if ((tid & 31) == 0) { sW[(tid>>5)] = ll; sW[8+(tid>>5)] = lc; sW[16+(tid>>5)] = np; }
    __syncthreads();
    if (tid == 0) {
        float L = 0, C = 0, N = 0;
        for (int w = 0; w < 8; w++) { L += sW[w]; C += sW[8+w]; N += sW[16+w]; }
        out[0] = L / N;
        out[1] = C / N;
    }
}

extern "C" void kernel_launch(void* const* d_in, const int* in_sizes, int n_in,
                              void* d_out, int out_size)
{
    const float* loc     = (const float*)d_in[0];
    const float* conf    = (const float*)d_in[1];
    const float* priors  = (const float*)d_in[2];
    const float* targets = (const float*)d_in[3];
    float* out = (float*)d_out;

    int B = in_sizes[3] / (NOBJ * 5);   // 256

    dim3 gA(NBLK_A, B);
    lse_kernel<<<gA, TA>>>(conf);
    multibox_loss_kernel<<<B, NT>>>(loc, conf, priors, targets, out, B);
    finalize_kernel<<<1, 256>>>(out, B);
}